// round 4
// baseline (speedup 1.0000x reference)
#include <cuda_runtime.h>

#define N_ELEMS 33554432
#define N4 (N_ELEMS / 4)   // 8388608 float4 work items
#define THREADS 256
#define NUM_CTAS 1184      // 148 SMs * 8 CTAs (256 thr, 32 regs) -> exactly 1 wave

__global__ __launch_bounds__(THREADS) void ssvi_kernel(
    const float4* __restrict__ logm,
    const float4* __restrict__ yATM,
    const float* __restrict__ raw_rho,
    const float* __restrict__ raw_eta,
    const float* __restrict__ raw_gamma,
    float4* __restrict__ out)
{
    // Broadcast scalars — computed once per thread, outside the loop.
    const float rho   = tanhf(__ldg(&raw_rho[0]));
    const float eta   = __expf(__ldg(&raw_eta[0]));
    const float gamma = __expf(__ldg(&raw_gamma[0]));
    const float one_m_rho2 = 1.0f - rho * rho;
    const float4 zero = make_float4(0.f, 0.f, 0.f, 0.f);

    const int stride = NUM_CTAS * THREADS;

    for (int i = blockIdx.x * THREADS + threadIdx.x; i < N4; i += stride) {
        float4 lm = __ldcs(&logm[i]);
        float4 y  = __ldcs(&yATM[i]);

        float4 o, g1, g2;

        #pragma unroll
        for (int c = 0; c < 4; ++c) {
            float lmv = (&lm.x)[c];
            float yv  = (&y.x)[c];

            // phi = eta / (y^gamma * (1+y)^(1-gamma))
            float ly  = __logf(yv);
            float l1y = __logf(1.0f + yv);
            float phi = eta * __expf(-(gamma * ly + (1.0f - gamma) * l1y));

            float pl  = phi * lmv;
            float arg = fmaf(pl, pl, fmaf(2.0f * rho, pl, 1.0f));  // pl^2 + 2 rho pl + 1
            float invS = rsqrtf(arg);
            float S    = arg * invS;
            float half_y = 0.5f * yv;

            (&o.x)[c]  = half_y * (1.0f + rho * pl + S);
            (&g1.x)[c] = half_y * phi * (rho + (pl + rho) * invS);
            float invS3 = invS * invS * invS;
            (&g2.x)[c] = half_y * phi * phi * one_m_rho2 * invS3;
        }

        __stcs(&out[i],          o);     // output
        __stcs(&out[N4 + i],     zero);  // grad_ttm1 (zeros; d_out is poisoned)
        __stcs(&out[2 * N4 + i], g1);    // grad_logm1
        __stcs(&out[3 * N4 + i], g2);    // grad_logm2
    }
}

extern "C" void kernel_launch(void* const* d_in, const int* in_sizes, int n_in,
                              void* d_out, int out_size)
{
    const float4* logm = (const float4*)d_in[0];
    const float4* yATM = (const float4*)d_in[1];
    const float* raw_rho   = (const float*)d_in[2];
    const float* raw_eta   = (const float*)d_in[3];
    const float* raw_gamma = (const float*)d_in[4];
    float4* out = (float4*)d_out;

    ssvi_kernel<<<NUM_CTAS, THREADS>>>(logm, yATM, raw_rho, raw_eta, raw_gamma, out);
}

// round 5
// speedup vs baseline: 1.0158x; 1.0158x over previous
#include <cuda_runtime.h>

#define N_ELEMS 33554432
#define N4 (N_ELEMS / 4)   // 8388608 float4 work items
#define THREADS 256

__global__ __launch_bounds__(THREADS) void ssvi_kernel(
    const float4* __restrict__ logm,
    const float4* __restrict__ yATM,
    const float* __restrict__ raw_rho,
    const float* __restrict__ raw_eta,
    const float* __restrict__ raw_gamma,
    float4* __restrict__ out)
{
    const int i = blockIdx.x * THREADS + threadIdx.x;  // grid exactly covers N4

    // Streaming loads — zero reuse.
    float4 lm = __ldcs(&logm[i]);
    float4 y  = __ldcs(&yATM[i]);

    // Independent zero store issued up front: starts the write stream draining
    // while the input loads + transcendentals are still in flight.
    out[N4 + i] = make_float4(0.f, 0.f, 0.f, 0.f);  // grad_ttm1

    // Broadcast scalars (tiny, cached)
    float rho   = tanhf(__ldg(&raw_rho[0]));
    float eta   = __expf(__ldg(&raw_eta[0]));
    float gamma = __expf(__ldg(&raw_gamma[0]));
    float one_m_rho2 = 1.0f - rho * rho;

    float4 o, g1, g2;

    #pragma unroll
    for (int c = 0; c < 4; ++c) {
        float lmv = (&lm.x)[c];
        float yv  = (&y.x)[c];

        // phi = eta / (y^gamma * (1+y)^(1-gamma))
        float ly  = __logf(yv);
        float l1y = __logf(1.0f + yv);
        float phi = eta * __expf(-(gamma * ly + (1.0f - gamma) * l1y));

        float pl  = phi * lmv;
        float arg = fmaf(pl, pl, fmaf(2.0f * rho, pl, 1.0f));  // pl^2 + 2 rho pl + 1
        float invS = rsqrtf(arg);
        float S    = arg * invS;
        float half_y = 0.5f * yv;

        (&o.x)[c]  = half_y * (1.0f + rho * pl + S);
        (&g1.x)[c] = half_y * phi * (rho + (pl + rho) * invS);
        float invS3 = invS * invS * invS;
        (&g2.x)[c] = half_y * phi * phi * one_m_rho2 * invS3;
    }

    out[i]          = o;     // output
    out[2 * N4 + i] = g1;    // grad_logm1
    out[3 * N4 + i] = g2;    // grad_logm2
}

extern "C" void kernel_launch(void* const* d_in, const int* in_sizes, int n_in,
                              void* d_out, int out_size)
{
    const float4* logm = (const float4*)d_in[0];
    const float4* yATM = (const float4*)d_in[1];
    const float* raw_rho   = (const float*)d_in[2];
    const float* raw_eta   = (const float*)d_in[3];
    const float* raw_gamma = (const float*)d_in[4];
    float4* out = (float4*)d_out;

    const int blocks = N4 / THREADS;  // exact: 2^23 / 256 = 32768
    ssvi_kernel<<<blocks, THREADS>>>(logm, yATM, raw_rho, raw_eta, raw_gamma, out);
}

// round 6
// speedup vs baseline: 1.0875x; 1.0706x over previous
#include <cuda_runtime.h>

#define N_ELEMS 33554432
#define N8 (N_ELEMS / 8)   // 4194304 8-float work items
#define THREADS 256

__device__ __forceinline__ void ldg256(const float* p, float r[8]) {
    asm("ld.global.nc.v8.f32 {%0,%1,%2,%3,%4,%5,%6,%7}, [%8];"
        : "=f"(r[0]), "=f"(r[1]), "=f"(r[2]), "=f"(r[3]),
          "=f"(r[4]), "=f"(r[5]), "=f"(r[6]), "=f"(r[7])
        : "l"(p));
}

__device__ __forceinline__ void stg256(float* p, const float r[8]) {
    asm volatile("st.global.v8.f32 [%0], {%1,%2,%3,%4,%5,%6,%7,%8};"
        :: "l"(p),
           "f"(r[0]), "f"(r[1]), "f"(r[2]), "f"(r[3]),
           "f"(r[4]), "f"(r[5]), "f"(r[6]), "f"(r[7])
        : "memory");
}

__global__ __launch_bounds__(THREADS) void ssvi_kernel(
    const float* __restrict__ logm,
    const float* __restrict__ yATM,
    const float* __restrict__ raw_rho,
    const float* __restrict__ raw_eta,
    const float* __restrict__ raw_gamma,
    float* __restrict__ out)
{
    const size_t base = ((size_t)blockIdx.x * THREADS + threadIdx.x) * 8;

    float lm[8], y[8];
    ldg256(logm + base, lm);
    ldg256(yATM + base, y);

    // Broadcast scalars (tiny, cached)
    const float rho   = tanhf(__ldg(&raw_rho[0]));
    const float eta   = __expf(__ldg(&raw_eta[0]));
    const float gamma = __expf(__ldg(&raw_gamma[0]));
    const float one_m_rho2 = 1.0f - rho * rho;

    float o[8], g1[8], g2[8];

    #pragma unroll
    for (int c = 0; c < 8; ++c) {
        float lmv = lm[c];
        float yv  = y[c];

        // phi = eta / (y^gamma * (1+y)^(1-gamma))
        float ly  = __logf(yv);
        float l1y = __logf(1.0f + yv);
        float phi = eta * __expf(-(gamma * ly + (1.0f - gamma) * l1y));

        float pl  = phi * lmv;
        float arg = fmaf(pl, pl, fmaf(2.0f * rho, pl, 1.0f));  // pl^2 + 2 rho pl + 1
        float invS = rsqrtf(arg);
        float S    = arg * invS;
        float half_y = 0.5f * yv;

        o[c]  = half_y * (1.0f + rho * pl + S);
        g1[c] = half_y * phi * (rho + (pl + rho) * invS);
        float invS3 = invS * invS * invS;
        g2[c] = half_y * phi * phi * one_m_rho2 * invS3;
    }

    const float z[8] = {0.f, 0.f, 0.f, 0.f, 0.f, 0.f, 0.f, 0.f};

    stg256(out + base,                        o);   // output
    stg256(out + (size_t)N_ELEMS + base,      z);   // grad_ttm1 (zeros; d_out poisoned)
    stg256(out + 2 * (size_t)N_ELEMS + base,  g1);  // grad_logm1
    stg256(out + 3 * (size_t)N_ELEMS + base,  g2);  // grad_logm2
}

extern "C" void kernel_launch(void* const* d_in, const int* in_sizes, int n_in,
                              void* d_out, int out_size)
{
    const float* logm = (const float*)d_in[0];
    const float* yATM = (const float*)d_in[1];
    const float* raw_rho   = (const float*)d_in[2];
    const float* raw_eta   = (const float*)d_in[3];
    const float* raw_gamma = (const float*)d_in[4];
    float* out = (float*)d_out;

    const int blocks = N8 / THREADS;  // exact: 4194304 / 256 = 16384
    ssvi_kernel<<<blocks, THREADS>>>(logm, yATM, raw_rho, raw_eta, raw_gamma, out);
}

// round 7
// speedup vs baseline: 1.0896x; 1.0019x over previous
#include <cuda_runtime.h>

#define N_ELEMS 33554432
#define N8 (N_ELEMS / 8)   // 4194304 8-float work items
#define THREADS 256

__device__ __forceinline__ void ldg256(const float* p, float r[8]) {
    asm("ld.global.nc.v8.f32 {%0,%1,%2,%3,%4,%5,%6,%7}, [%8];"
        : "=f"(r[0]), "=f"(r[1]), "=f"(r[2]), "=f"(r[3]),
          "=f"(r[4]), "=f"(r[5]), "=f"(r[6]), "=f"(r[7])
        : "l"(p));
}

__device__ __forceinline__ void stg256(float* p, const float r[8]) {
    asm volatile("st.global.v8.f32 [%0], {%1,%2,%3,%4,%5,%6,%7,%8};"
        :: "l"(p),
           "f"(r[0]), "f"(r[1]), "f"(r[2]), "f"(r[3]),
           "f"(r[4]), "f"(r[5]), "f"(r[6]), "f"(r[7])
        : "memory");
}

__global__ __launch_bounds__(THREADS) void ssvi_kernel(
    const float* __restrict__ logm,
    const float* __restrict__ yATM,
    const float* __restrict__ raw_rho,
    const float* __restrict__ raw_eta,
    const float* __restrict__ raw_gamma,
    float* __restrict__ out)
{
    const size_t base = ((size_t)blockIdx.x * THREADS + threadIdx.x) * 8;

    float lm[8], y[8];
    ldg256(logm + base, lm);
    ldg256(yATM + base, y);

    // Broadcast scalars (tiny, cached)
    const float rho   = tanhf(__ldg(&raw_rho[0]));
    const float eta   = __expf(__ldg(&raw_eta[0]));
    const float gamma = __expf(__ldg(&raw_gamma[0]));
    const float one_m_rho2 = 1.0f - rho * rho;

    float o[8], g1[8], g2[8];

    #pragma unroll
    for (int c = 0; c < 8; ++c) {
        float lmv = lm[c];
        float yv  = y[c];

        // phi = eta / (y^gamma * (1+y)^(1-gamma))
        float ly  = __logf(yv);
        float l1y = __logf(1.0f + yv);
        float phi = eta * __expf(-(gamma * ly + (1.0f - gamma) * l1y));

        float pl  = phi * lmv;
        float arg = fmaf(pl, pl, fmaf(2.0f * rho, pl, 1.0f));  // pl^2 + 2 rho pl + 1
        float invS = rsqrtf(arg);
        float S    = arg * invS;
        float half_y = 0.5f * yv;

        o[c]  = half_y * (1.0f + rho * pl + S);
        g1[c] = half_y * phi * (rho + (pl + rho) * invS);
        float invS3 = invS * invS * invS;
        g2[c] = half_y * phi * phi * one_m_rho2 * invS3;
    }

    const float z[8] = {0.f, 0.f, 0.f, 0.f, 0.f, 0.f, 0.f, 0.f};

    stg256(out + base,                        o);   // output
    stg256(out + (size_t)N_ELEMS + base,      z);   // grad_ttm1 (zeros; d_out poisoned)
    stg256(out + 2 * (size_t)N_ELEMS + base,  g1);  // grad_logm1
    stg256(out + 3 * (size_t)N_ELEMS + base,  g2);  // grad_logm2
}

extern "C" void kernel_launch(void* const* d_in, const int* in_sizes, int n_in,
                              void* d_out, int out_size)
{
    const float* logm = (const float*)d_in[0];
    const float* yATM = (const float*)d_in[1];
    const float* raw_rho   = (const float*)d_in[2];
    const float* raw_eta   = (const float*)d_in[3];
    const float* raw_gamma = (const float*)d_in[4];
    float* out = (float*)d_out;

    const int blocks = N8 / THREADS;  // exact: 4194304 / 256 = 16384
    ssvi_kernel<<<blocks, THREADS>>>(logm, yATM, raw_rho, raw_eta, raw_gamma, out);
}